// round 7
// baseline (speedup 1.0000x reference)
#include <cuda_runtime.h>
#include <cuda_bf16.h>
#include <cuda_fp8.h>
#include <cstdint>

#define D        256
#define N2MAX    8192
#define TILE     128
#define NB       64
#define NTILES   2080                 // NB*(NB+1)/2
#define NCTA     148
#define SSTRB    272                  // 256 B row + 16 B pad (odd # of 16B units)
#define SBYTES   (TILE * SSTRB)       // 34816 B per fp8 tile

__device__ __align__(16) uint8_t g_zn[N2MAX * D];   // e4m3, scaled by 16
__device__ float g_S[N2MAX];
__device__ float g_pos[N2MAX / 2];

__device__ __forceinline__ uint32_t smem_u32(const void* p) {
    uint32_t a;
    asm("{ .reg .u64 t; cvta.to.shared.u64 t, %1; cvt.u32.u64 %0, t; }" : "=r"(a) : "l"(p));
    return a;
}
#define CP_ASYNC16(d, s) \
    asm volatile("cp.async.cg.shared.global [%0], [%1], 16;" :: "r"(d), "l"(s) : "memory")
#define CP_COMMIT()  asm volatile("cp.async.commit_group;" ::: "memory")
#define CP_WAIT0()   asm volatile("cp.async.wait_group 0;" ::: "memory")
#define LDSM4(r0, r1, r2, r3, a) \
    asm volatile("ldmatrix.sync.aligned.m8n8.x4.shared.b16 {%0,%1,%2,%3}, [%4];" \
                 : "=r"(r0), "=r"(r1), "=r"(r2), "=r"(r3) : "r"(a))
#define MMAQ(d, a, b) \
    asm volatile("mma.sync.aligned.m16n8k32.row.col.f32.e4m3.e4m3.f32 " \
                 "{%0,%1,%2,%3},{%4,%5,%6,%7},{%8,%9},{%0,%1,%2,%3};" \
                 : "+f"((d)[0]), "+f"((d)[1]), "+f"((d)[2]), "+f"((d)[3]) \
                 : "r"((a)[0]), "r"((a)[1]), "r"((a)[2]), "r"((a)[3]), \
                   "r"((b)[0]), "r"((b)[1]))

#define EC1 0.69314718f
#define EC2 0.24022651f
#define EC3 0.05550411f
#define EC4 0.00961813f
// acc = 256*dot (rows scaled by 16); e = exp(2*dot - 2) = exp2(acc/128*log2e - 2log2e)
#define EXPSTEP(x, e) { \
    float y = fmaf((x), 0.011270992507f, -2.8853900818f); \
    float z = __fadd_rn(y, 12582912.0f); \
    float f = y - __fadd_rn(z, -12582912.0f); \
    float p = fmaf(f, EC4, EC3); \
    p = fmaf(f, p, EC2); \
    p = fmaf(f, p, EC1); \
    p = fmaf(f, p, 1.0f); \
    (e) = __int_as_float(__float_as_int(p) + (__float_as_int(z) << 23)); }

__device__ __forceinline__ uint32_t pack_e4m3(float x, float y, float z, float w) {
    __nv_fp8x2_storage_t lo =
        __nv_cvt_float2_to_fp8x2(make_float2(x, y), __NV_SATFINITE, __NV_E4M3);
    __nv_fp8x2_storage_t hi =
        __nv_cvt_float2_to_fp8x2(make_float2(z, w), __NV_SATFINITE, __NV_E4M3);
    return (uint32_t)lo | ((uint32_t)hi << 16);
}

// copy one 128x256B fp8 tile into padded smem (2048 16B chunks, 8/thread)
__device__ __forceinline__ void load_tile_async(uint32_t sbase, int row0, int tid) {
    #pragma unroll
    for (int i = 0; i < 8; i++) {
        int chunk = i * 256 + tid;
        int r   = chunk >> 4;
        int c16 = chunk & 15;
        const char* src = (const char*)(g_zn + (size_t)(row0 + r) * D) + c16 * 16;
        CP_ASYNC16(sbase + (uint32_t)(r * SSTRB + c16 * 16), src);
    }
}

__device__ __forceinline__ void map_tile(int T, int& i, int& j) {
    int pair = T / 65;
    int s    = T - pair * 65;
    int n1   = NB - pair;
    if (s < n1) { i = pair;          j = pair + s; }
    else        { i = NB - 1 - pair; j = i + (s - n1); }
}

// k-loop for one 128x128 tile (8 k-steps of 32); optional interleaved epilogue
// of the previous tile (8 prev values per k-step).
template<bool EPI>
__device__ __forceinline__ void mma_tile(
    uint32_t aAddr, uint32_t bAddr,
    float (&acc)[16][4], float (&prev)[16][4],
    float (&rs)[8], float (&cs)[8])
{
    #pragma unroll
    for (int q = 0; q < 16; q++)
        #pragma unroll
        for (int v = 0; v < 4; v++) acc[q][v] = 0.0f;
    #pragma unroll
    for (int ks = 0; ks < 8; ks++) {
        uint32_t a[4][4], b[4][2];
        #pragma unroll
        for (int mt = 0; mt < 4; mt++)
            LDSM4(a[mt][0], a[mt][1], a[mt][2], a[mt][3],
                  aAddr + (uint32_t)(mt * 16 * SSTRB + ks * 32));
        #pragma unroll
        for (int np = 0; np < 2; np++)
            LDSM4(b[np*2][0], b[np*2][1], b[np*2+1][0], b[np*2+1][1],
                  bAddr + (uint32_t)(np * 16 * SSTRB + ks * 32));
        #pragma unroll
        for (int mt = 0; mt < 4; mt++)
            #pragma unroll
            for (int nt = 0; nt < 4; nt++)
                MMAQ(acc[mt * 4 + nt], a[mt], b[nt]);
        if (EPI) {
            #pragma unroll
            for (int h = 0; h < 2; h++) {
                const int q = ks * 2 + h, mt = q >> 2, nt = q & 3;
                #pragma unroll
                for (int v = 0; v < 4; v++) {
                    float e;
                    EXPSTEP(prev[q][v], e);
                    rs[mt * 2 + (v >> 1)] += e;
                    cs[nt * 2 + (v & 1)]  += e;
                }
            }
        }
    }
}

// ---------------------------------------------------------------------------
// K1: normalize pair (r, r+N) -> e4m3 (x16); exact fp32 positive sim; zero g_S.
// ---------------------------------------------------------------------------
__global__ void __launch_bounds__(128) normalize_kernel(
    const float* __restrict__ zi, const float* __restrict__ zj, int N)
{
    int gidx = blockIdx.x * 128 + threadIdx.x;
    if (gidx < N2MAX) g_S[gidx] = 0.0f;

    int warp = threadIdx.x >> 5, lane = threadIdx.x & 31;
    int r = blockIdx.x * 4 + warp;
    if (r >= N) return;
    const float4* a = (const float4*)(zi + (size_t)r * D);
    const float4* b = (const float4*)(zj + (size_t)r * D);
    float4 a0 = a[lane], a1 = a[lane + 32];
    float4 b0 = b[lane], b1 = b[lane + 32];
    float sa = a0.x*a0.x+a0.y*a0.y+a0.z*a0.z+a0.w*a0.w + a1.x*a1.x+a1.y*a1.y+a1.z*a1.z+a1.w*a1.w;
    float sb = b0.x*b0.x+b0.y*b0.y+b0.z*b0.z+b0.w*b0.w + b1.x*b1.x+b1.y*b1.y+b1.z*b1.z+b1.w*b1.w;
    float dt = a0.x*b0.x+a0.y*b0.y+a0.z*b0.z+a0.w*b0.w + a1.x*b1.x+a1.y*b1.y+a1.z*b1.z+a1.w*b1.w;
    #pragma unroll
    for (int m = 16; m; m >>= 1) {
        sa += __shfl_xor_sync(0xffffffffu, sa, m);
        sb += __shfl_xor_sync(0xffffffffu, sb, m);
        dt += __shfl_xor_sync(0xffffffffu, dt, m);
    }
    float na = fmaxf(sqrtf(sa), 1e-8f);
    float nb = fmaxf(sqrtf(sb), 1e-8f);
    if (lane == 0) g_pos[r] = 2.0f * dt / (na * nb);

    float ia = 16.0f / na;      // scale into e4m3 sweet spot
    float ib = 16.0f / nb;
    uint32_t* oa = (uint32_t*)(g_zn + (size_t)r * D);
    oa[lane]      = pack_e4m3(a0.x*ia, a0.y*ia, a0.z*ia, a0.w*ia);
    oa[lane + 32] = pack_e4m3(a1.x*ia, a1.y*ia, a1.z*ia, a1.w*ia);
    uint32_t* ob = (uint32_t*)(g_zn + (size_t)(r + N) * D);
    ob[lane]      = pack_e4m3(b0.x*ib, b0.y*ib, b0.z*ib, b0.w*ib);
    ob[lane + 32] = pack_e4m3(b1.x*ib, b1.y*ib, b1.z*ib, b1.w*ib);
}

// ---------------------------------------------------------------------------
// K2: triangular FP8 QMMA GEMM, 148 CTAs, A+B both double-buffered,
// previous-tile epilogue pipelined under the k-loop.
// ---------------------------------------------------------------------------
__global__ void __launch_bounds__(256, 1) sim_kernel()
{
    extern __shared__ char sm[];
    const int tid  = threadIdx.x;
    const int wid  = tid >> 5;
    const int lane = tid & 31;
    const int wm   = wid & 1;
    const int wn   = wid >> 1;

    const int lo = (NTILES * blockIdx.x) / NCTA;
    const int hi = (NTILES * (blockIdx.x + 1)) / NCTA;

    const uint32_t base = smem_u32(sm);
    const uint32_t aBuf[2] = { base, base + SBYTES };
    const uint32_t bBuf[2] = { base + 2 * SBYTES, base + 3 * SBYTES };

    const uint32_t aOff =
        (uint32_t)((wm * 64 + (lane & 15)) * SSTRB + (lane >> 4) * 16);
    const uint32_t bOff =
        (uint32_t)((wn * 32 + (lane & 7) + ((lane >> 4) << 3)) * SSTRB +
                   ((lane >> 3) & 1) * 16);

    float acc[16][4], prev[16][4];
    float rs[8] = {0,0,0,0,0,0,0,0};
    float cs[8];

    int i, j;
    map_tile(lo, i, j);
    load_tile_async(aBuf[0], i * TILE, tid);
    load_tile_async(bBuf[0], j * TILE, tid);
    CP_COMMIT(); CP_WAIT0();
    __syncthreads();
    int aCur = 0;

    // --- peeled first tile ---
    int ni = -1, nj = -1;
    if (lo + 1 < hi) {
        map_tile(lo + 1, ni, nj);
        load_tile_async(bBuf[1], nj * TILE, tid);
        if (ni != i) load_tile_async(aBuf[1], ni * TILE, tid);
        CP_COMMIT();
    }
    mma_tile<false>(aBuf[aCur] + aOff, bBuf[0] + bOff, acc, prev, rs, cs);
    #pragma unroll
    for (int q = 0; q < 16; q++)
        #pragma unroll
        for (int v = 0; v < 4; v++) prev[q][v] = acc[q][v];
    int iP = i, jP = j;
    if (lo + 1 < hi) {
        CP_WAIT0(); __syncthreads();
        if (ni != i) aCur = 1;
    }
    i = ni; j = nj;

    for (int t = lo + 1; t < hi; t++) {
        const int bIdx = (t - lo) & 1;
        const int curI = i, curJ = j;
        int ti = -1, tj = -1;
        if (t + 1 < hi) {
            map_tile(t + 1, ti, tj);
            load_tile_async(bBuf[bIdx ^ 1], tj * TILE, tid);
            if (ti != curI) load_tile_async(aBuf[aCur ^ 1], ti * TILE, tid);
            CP_COMMIT();
        }

        #pragma unroll
        for (int q = 0; q < 8; q++) cs[q] = 0.0f;
        mma_tile<true>(aBuf[aCur] + aOff, bBuf[bIdx] + bOff, acc, prev, rs, cs);

        // finish tile t-1
        if (jP != iP) {
            #pragma unroll
            for (int q = 0; q < 8; q++) {
                cs[q] += __shfl_xor_sync(0xffffffffu, cs[q], 4);
                cs[q] += __shfl_xor_sync(0xffffffffu, cs[q], 8);
                cs[q] += __shfl_xor_sync(0xffffffffu, cs[q], 16);
            }
            if (lane < 4) {
                const int C0 = jP * TILE + wn * 32 + lane * 2;
                #pragma unroll
                for (int nt = 0; nt < 4; nt++) {
                    atomicAdd(&g_S[C0 + nt * 8],     cs[nt * 2]);
                    atomicAdd(&g_S[C0 + nt * 8 + 1], cs[nt * 2 + 1]);
                }
            }
        }
        if (iP != curI) {
            #pragma unroll
            for (int q = 0; q < 8; q++) {
                rs[q] += __shfl_xor_sync(0xffffffffu, rs[q], 1);
                rs[q] += __shfl_xor_sync(0xffffffffu, rs[q], 2);
            }
            if ((lane & 3) == 0) {
                const int R0 = iP * TILE + wm * 64;
                #pragma unroll
                for (int mt = 0; mt < 4; mt++) {
                    atomicAdd(&g_S[R0 + mt * 16 +     (lane >> 2)], rs[mt * 2]);
                    atomicAdd(&g_S[R0 + mt * 16 + 8 + (lane >> 2)], rs[mt * 2 + 1]);
                }
            }
            #pragma unroll
            for (int q = 0; q < 8; q++) rs[q] = 0.0f;
        }

        #pragma unroll
        for (int q = 0; q < 16; q++)
            #pragma unroll
            for (int v = 0; v < 4; v++) prev[q][v] = acc[q][v];
        iP = curI; jP = curJ;

        if (t + 1 < hi) {
            CP_WAIT0(); __syncthreads();
            if (ti != curI) aCur ^= 1;
        }
        i = ti; j = tj;
    }

    // --- drain epilogue of last tile ---
    #pragma unroll
    for (int q = 0; q < 8; q++) cs[q] = 0.0f;
    #pragma unroll
    for (int q = 0; q < 16; q++) {
        const int mt = q >> 2, nt = q & 3;
        #pragma unroll
        for (int v = 0; v < 4; v++) {
            float e;
            EXPSTEP(prev[q][v], e);
            rs[mt * 2 + (v >> 1)] += e;
            cs[nt * 2 + (v & 1)]  += e;
        }
    }
    if (jP != iP) {
        #pragma unroll
        for (int q = 0; q < 8; q++) {
            cs[q] += __shfl_xor_sync(0xffffffffu, cs[q], 4);
            cs[q] += __shfl_xor_sync(0xffffffffu, cs[q], 8);
            cs[q] += __shfl_xor_sync(0xffffffffu, cs[q], 16);
        }
        if (lane < 4) {
            const int C0 = jP * TILE + wn * 32 + lane * 2;
            #pragma unroll
            for (int nt = 0; nt < 4; nt++) {
                atomicAdd(&g_S[C0 + nt * 8],     cs[nt * 2]);
                atomicAdd(&g_S[C0 + nt * 8 + 1], cs[nt * 2 + 1]);
            }
        }
    }
    #pragma unroll
    for (int q = 0; q < 8; q++) {
        rs[q] += __shfl_xor_sync(0xffffffffu, rs[q], 1);
        rs[q] += __shfl_xor_sync(0xffffffffu, rs[q], 2);
    }
    if ((lane & 3) == 0) {
        const int R0 = iP * TILE + wm * 64;
        #pragma unroll
        for (int mt = 0; mt < 4; mt++) {
            atomicAdd(&g_S[R0 + mt * 16 +     (lane >> 2)], rs[mt * 2]);
            atomicAdd(&g_S[R0 + mt * 16 + 8 + (lane >> 2)], rs[mt * 2 + 1]);
        }
    }
}

// ---------------------------------------------------------------------------
// K3: loss = [sum_i (2 + log(S_i - 1)) - 2*sum_r pos_r] / 2N
// ---------------------------------------------------------------------------
__global__ void __launch_bounds__(1024) reduce_kernel(float* __restrict__ out, int N2)
{
    __shared__ double sh[1024];
    double local = 0.0;
    for (int i = threadIdx.x; i < N2; i += 1024)
        local += (double)(2.0f + __logf(g_S[i] - 1.0f));
    for (int r = threadIdx.x; r < N2 / 2; r += 1024)
        local -= 2.0 * (double)g_pos[r];
    sh[threadIdx.x] = local;
    __syncthreads();
    #pragma unroll
    for (int s2 = 512; s2; s2 >>= 1) {
        if (threadIdx.x < s2) sh[threadIdx.x] += sh[threadIdx.x + s2];
        __syncthreads();
    }
    if (threadIdx.x == 0) out[0] = (float)(sh[0] / (double)N2);
}

// ---------------------------------------------------------------------------
extern "C" void kernel_launch(void* const* d_in, const int* in_sizes, int n_in,
                              void* d_out, int out_size)
{
    const float* zi = (const float*)d_in[0];
    const float* zj = (const float*)d_in[1];
    int N  = in_sizes[0] / D;     // 4096
    int N2 = 2 * N;               // 8192

    normalize_kernel<<<(N + 3) / 4, 128>>>(zi, zj, N);

    size_t smem = 4 * (size_t)SBYTES;   // 139264 B
    cudaFuncSetAttribute(sim_kernel,
                         cudaFuncAttributeMaxDynamicSharedMemorySize, (int)smem);
    sim_kernel<<<NCTA, 256, smem>>>();

    reduce_kernel<<<1, 1024>>>((float*)d_out, N2);
}

// round 8
// speedup vs baseline: 1.0936x; 1.0936x over previous
#include <cuda_runtime.h>
#include <cuda_bf16.h>
#include <cstdint>

#define D        256
#define N2MAX    8192
#define TILE     128
#define NB       64
#define NTILES   2080                 // NB*(NB+1)/2
#define NCTA     148
#define NWARPS   (NCTA * 8)
#define PAD      8
#define SSTRIDE  (D + PAD)            // 264 bf16 (odd # of 16B units)
#define SBYTES   (TILE * SSTRIDE * 2) // 67584 B per tile

__device__ __align__(16) __nv_bfloat16 g_zn[N2MAX * D];
__device__ float g_S[N2MAX];
__device__ float g_pos[N2MAX / 2];
__device__ int   g_c1 = 0, g_c2 = 0;   // grid barriers (reset by CTA0 each launch)

__device__ __forceinline__ uint32_t smem_u32(const void* p) {
    uint32_t a;
    asm("{ .reg .u64 t; cvta.to.shared.u64 t, %1; cvt.u32.u64 %0, t; }" : "=r"(a) : "l"(p));
    return a;
}
#define CP_ASYNC16(d, s) \
    asm volatile("cp.async.cg.shared.global [%0], [%1], 16;" :: "r"(d), "l"(s) : "memory")
#define CP_COMMIT()  asm volatile("cp.async.commit_group;" ::: "memory")
#define CP_WAIT0()   asm volatile("cp.async.wait_group 0;" ::: "memory")
#define LDSM4(r0, r1, r2, r3, a) \
    asm volatile("ldmatrix.sync.aligned.m8n8.x4.shared.b16 {%0,%1,%2,%3}, [%4];" \
                 : "=r"(r0), "=r"(r1), "=r"(r2), "=r"(r3) : "r"(a))
#define MMA(d, a, b) \
    asm volatile("mma.sync.aligned.m16n8k16.row.col.f32.bf16.bf16.f32 " \
                 "{%0,%1,%2,%3},{%4,%5,%6,%7},{%8,%9},{%0,%1,%2,%3};" \
                 : "+f"((d)[0]), "+f"((d)[1]), "+f"((d)[2]), "+f"((d)[3]) \
                 : "r"((a)[0]), "r"((a)[1]), "r"((a)[2]), "r"((a)[3]), \
                   "r"((b)[0]), "r"((b)[1]))

#define EC1 0.69314718f
#define EC2 0.24022651f
#define EC3 0.05550411f
#define EC4 0.00961813f
// e = exp(2*x - 2) via exp2 polynomial (no MUFU)
#define EXPSTEP(x, e) { \
    float y = fmaf((x), 2.8853901f, -2.8853901f); \
    float z = __fadd_rn(y, 12582912.0f); \
    float f = y - __fadd_rn(z, -12582912.0f); \
    float p = fmaf(f, EC4, EC3); \
    p = fmaf(f, p, EC2); \
    p = fmaf(f, p, EC1); \
    p = fmaf(f, p, 1.0f); \
    (e) = __int_as_float(__float_as_int(p) + (__float_as_int(z) << 23)); }

__device__ __forceinline__ void load_tile_async(uint32_t sbase, int row0, int tid) {
    #pragma unroll
    for (int i = 0; i < 16; i++) {
        int chunk = i * 256 + tid;
        int r   = chunk >> 5;
        int c16 = chunk & 31;
        const char* src = (const char*)(g_zn + (size_t)(row0 + r) * D) + c16 * 16;
        CP_ASYNC16(sbase + (uint32_t)(r * (SSTRIDE * 2) + c16 * 16), src);
    }
}

__device__ __forceinline__ void map_tile(int T, int& i, int& j) {
    int pair = T / 65;
    int s    = T - pair * 65;
    int n1   = NB - pair;
    if (s < n1) { i = pair;          j = pair + s; }
    else        { i = NB - 1 - pair; j = i + (s - n1); }
}

template<bool EPI>
__device__ __forceinline__ void mma_tile(
    uint32_t aAddr, uint32_t bAddr,
    float (&acc)[16][4], float (&prev)[16][4],
    float (&rs)[8], float (&cs)[8])
{
    #pragma unroll
    for (int q = 0; q < 16; q++)
        #pragma unroll
        for (int v = 0; v < 4; v++) acc[q][v] = 0.0f;
    #pragma unroll
    for (int ks = 0; ks < 16; ks++) {
        uint32_t a[4][4], b[4][2];
        #pragma unroll
        for (int mt = 0; mt < 4; mt++)
            LDSM4(a[mt][0], a[mt][1], a[mt][2], a[mt][3],
                  aAddr + (uint32_t)(mt * 16 * (SSTRIDE * 2) + ks * 32));
        #pragma unroll
        for (int np = 0; np < 2; np++)
            LDSM4(b[np*2][0], b[np*2][1], b[np*2+1][0], b[np*2+1][1],
                  bAddr + (uint32_t)(np * 16 * (SSTRIDE * 2) + ks * 32));
        #pragma unroll
        for (int mt = 0; mt < 4; mt++)
            #pragma unroll
            for (int nt = 0; nt < 4; nt++)
                MMA(acc[mt * 4 + nt], a[mt], b[nt]);
        if (EPI) {
            const int q = ks, mt = ks >> 2, nt = ks & 3;
            #pragma unroll
            for (int v = 0; v < 4; v++) {
                float e;
                EXPSTEP(prev[q][v], e);
                rs[mt * 2 + (v >> 1)] += e;
                cs[nt * 2 + (v & 1)]  += e;
            }
        }
    }
}

// ---------------------------------------------------------------------------
// Single fused kernel: normalize -> grid barrier -> triangular GEMM+epilogue
// -> grid barrier -> CTA0 reduce.  148 co-resident CTAs (1/SM, smem-capped).
// ---------------------------------------------------------------------------
__global__ void __launch_bounds__(256, 1) fused_kernel(
    const float* __restrict__ zi, const float* __restrict__ zj,
    float* __restrict__ out, int N)
{
    extern __shared__ char sm[];
    const int tid  = threadIdx.x;
    const int wid  = tid >> 5;
    const int lane = tid & 31;
    const int N2   = 2 * N;

    // ---- Phase A: zero g_S + normalize (all CTAs share the row-pairs) ----
    for (int idx = blockIdx.x * 256 + tid; idx < N2; idx += NCTA * 256)
        g_S[idx] = 0.0f;

    for (int r = blockIdx.x * 8 + wid; r < N; r += NWARPS) {
        const float4* a = (const float4*)(zi + (size_t)r * D);
        const float4* b = (const float4*)(zj + (size_t)r * D);
        float4 a0 = a[lane], a1 = a[lane + 32];
        float4 b0 = b[lane], b1 = b[lane + 32];
        float sa = a0.x*a0.x+a0.y*a0.y+a0.z*a0.z+a0.w*a0.w + a1.x*a1.x+a1.y*a1.y+a1.z*a1.z+a1.w*a1.w;
        float sb = b0.x*b0.x+b0.y*b0.y+b0.z*b0.z+b0.w*b0.w + b1.x*b1.x+b1.y*b1.y+b1.z*b1.z+b1.w*b1.w;
        float dt = a0.x*b0.x+a0.y*b0.y+a0.z*b0.z+a0.w*b0.w + a1.x*b1.x+a1.y*b1.y+a1.z*b1.z+a1.w*b1.w;
        #pragma unroll
        for (int m = 16; m; m >>= 1) {
            sa += __shfl_xor_sync(0xffffffffu, sa, m);
            sb += __shfl_xor_sync(0xffffffffu, sb, m);
            dt += __shfl_xor_sync(0xffffffffu, dt, m);
        }
        float na = fmaxf(sqrtf(sa), 1e-8f);
        float nb = fmaxf(sqrtf(sb), 1e-8f);
        if (lane == 0) g_pos[r] = 2.0f * dt / (na * nb);
        float ia = 1.0f / na, ib = 1.0f / nb;
        __nv_bfloat162* oa = (__nv_bfloat162*)(g_zn + (size_t)r * D);
        oa[2*lane]      = __nv_bfloat162(__float2bfloat16_rn(a0.x*ia), __float2bfloat16_rn(a0.y*ia));
        oa[2*lane + 1]  = __nv_bfloat162(__float2bfloat16_rn(a0.z*ia), __float2bfloat16_rn(a0.w*ia));
        oa[2*lane + 64] = __nv_bfloat162(__float2bfloat16_rn(a1.x*ia), __float2bfloat16_rn(a1.y*ia));
        oa[2*lane + 65] = __nv_bfloat162(__float2bfloat16_rn(a1.z*ia), __float2bfloat16_rn(a1.w*ia));
        __nv_bfloat162* ob = (__nv_bfloat162*)(g_zn + (size_t)(r + N) * D);
        ob[2*lane]      = __nv_bfloat162(__float2bfloat16_rn(b0.x*ib), __float2bfloat16_rn(b0.y*ib));
        ob[2*lane + 1]  = __nv_bfloat162(__float2bfloat16_rn(b0.z*ib), __float2bfloat16_rn(b0.w*ib));
        ob[2*lane + 64] = __nv_bfloat162(__float2bfloat16_rn(b1.x*ib), __float2bfloat16_rn(b1.y*ib));
        ob[2*lane + 65] = __nv_bfloat162(__float2bfloat16_rn(b1.z*ib), __float2bfloat16_rn(b1.w*ib));
    }

    // ---- grid barrier 1 (all 148 CTAs co-resident; counter reset at end) ----
    __syncthreads();
    if (tid == 0) {
        __threadfence();
        atomicAdd(&g_c1, 1);
        while (atomicAdd(&g_c1, 0) < NCTA) { }
        __threadfence();
    }
    __syncthreads();

    // ---- Phase B: triangular GEMM with pipelined epilogue (round-6 body) ----
    {
        const int wm = wid & 1;
        const int wn = wid >> 1;
        const int lo = (NTILES * blockIdx.x) / NCTA;
        const int hi = (NTILES * (blockIdx.x + 1)) / NCTA;

        const uint32_t aB  = smem_u32(sm);
        const uint32_t bB0 = aB + SBYTES;
        const uint32_t bB1 = aB + 2 * SBYTES;
        const uint32_t aAddr = aB +
            (uint32_t)((wm * 64 + (lane & 15)) * (SSTRIDE * 2) + (lane >> 4) * 16);
        const uint32_t bOff =
            (uint32_t)((wn * 32 + (lane & 7) + ((lane >> 4) << 3)) * (SSTRIDE * 2) +
                       ((lane >> 3) & 1) * 16);

        float acc[16][4], prev[16][4];
        float rs[8] = {0,0,0,0,0,0,0,0};
        float cs[8];

        int i, j;
        map_tile(lo, i, j);
        load_tile_async(aB, i * TILE, tid);
        load_tile_async(bB0, j * TILE, tid);
        CP_COMMIT(); CP_WAIT0();
        __syncthreads();

        int ni = -1, nj = -1;
        if (lo + 1 < hi) {
            map_tile(lo + 1, ni, nj);
            load_tile_async(bB1, nj * TILE, tid);
            CP_COMMIT();
        }
        mma_tile<false>(aAddr, bB0 + bOff, acc, prev, rs, cs);
        #pragma unroll
        for (int q = 0; q < 16; q++)
            #pragma unroll
            for (int v = 0; v < 4; v++) prev[q][v] = acc[q][v];
        int iP = i, jP = j;
        if (lo + 1 < hi) {
            if (ni != i) { __syncthreads(); load_tile_async(aB, ni * TILE, tid); CP_COMMIT(); }
            CP_WAIT0(); __syncthreads();
        }

        int pb = 1;
        for (int t = lo + 1; t < hi; t++) {
            i = ni; j = nj;
            if (t + 1 < hi) {
                map_tile(t + 1, ni, nj);
                load_tile_async(pb ? bB0 : bB1, nj * TILE, tid);
                CP_COMMIT();
            } else ni = -1;

            #pragma unroll
            for (int q = 0; q < 8; q++) cs[q] = 0.0f;
            mma_tile<true>(aAddr, (pb ? bB1 : bB0) + bOff, acc, prev, rs, cs);

            if (jP != iP) {
                #pragma unroll
                for (int q = 0; q < 8; q++) {
                    cs[q] += __shfl_xor_sync(0xffffffffu, cs[q], 4);
                    cs[q] += __shfl_xor_sync(0xffffffffu, cs[q], 8);
                    cs[q] += __shfl_xor_sync(0xffffffffu, cs[q], 16);
                }
                if (lane < 4) {
                    const int C0 = jP * TILE + wn * 32 + lane * 2;
                    #pragma unroll
                    for (int nt = 0; nt < 4; nt++) {
                        atomicAdd(&g_S[C0 + nt * 8],     cs[nt * 2]);
                        atomicAdd(&g_S[C0 + nt * 8 + 1], cs[nt * 2 + 1]);
                    }
                }
            }
            if (iP != i) {
                #pragma unroll
                for (int q = 0; q < 8; q++) {
                    rs[q] += __shfl_xor_sync(0xffffffffu, rs[q], 1);
                    rs[q] += __shfl_xor_sync(0xffffffffu, rs[q], 2);
                }
                if ((lane & 3) == 0) {
                    const int R0 = iP * TILE + wm * 64;
                    #pragma unroll
                    for (int mt = 0; mt < 4; mt++) {
                        atomicAdd(&g_S[R0 + mt * 16 +     (lane >> 2)], rs[mt * 2]);
                        atomicAdd(&g_S[R0 + mt * 16 + 8 + (lane >> 2)], rs[mt * 2 + 1]);
                    }
                }
                #pragma unroll
                for (int q = 0; q < 8; q++) rs[q] = 0.0f;
            }

            #pragma unroll
            for (int q = 0; q < 16; q++)
                #pragma unroll
                for (int v = 0; v < 4; v++) prev[q][v] = acc[q][v];
            iP = i; jP = j;

            if (t + 1 < hi) {
                if (ni != i) { __syncthreads(); load_tile_async(aB, ni * TILE, tid); CP_COMMIT(); }
                CP_WAIT0(); __syncthreads();
            }
            pb ^= 1;
        }

        // drain
        #pragma unroll
        for (int q = 0; q < 8; q++) cs[q] = 0.0f;
        #pragma unroll
        for (int q = 0; q < 16; q++) {
            const int mt = q >> 2, nt = q & 3;
            #pragma unroll
            for (int v = 0; v < 4; v++) {
                float e;
                EXPSTEP(prev[q][v], e);
                rs[mt * 2 + (v >> 1)] += e;
                cs[nt * 2 + (v & 1)]  += e;
            }
        }
        if (jP != iP) {
            #pragma unroll
            for (int q = 0; q < 8; q++) {
                cs[q] += __shfl_xor_sync(0xffffffffu, cs[q], 4);
                cs[q] += __shfl_xor_sync(0xffffffffu, cs[q], 8);
                cs[q] += __shfl_xor_sync(0xffffffffu, cs[q], 16);
            }
            if (lane < 4) {
                const int C0 = jP * TILE + wn * 32 + lane * 2;
                #pragma unroll
                for (int nt = 0; nt < 4; nt++) {
                    atomicAdd(&g_S[C0 + nt * 8],     cs[nt * 2]);
                    atomicAdd(&g_S[C0 + nt * 8 + 1], cs[nt * 2 + 1]);
                }
            }
        }
        #pragma unroll
        for (int q = 0; q < 8; q++) {
            rs[q] += __shfl_xor_sync(0xffffffffu, rs[q], 1);
            rs[q] += __shfl_xor_sync(0xffffffffu, rs[q], 2);
        }
        if ((lane & 3) == 0) {
            const int R0 = iP * TILE + wm * 64;
            #pragma unroll
            for (int mt = 0; mt < 4; mt++) {
                atomicAdd(&g_S[R0 + mt * 16 +     (lane >> 2)], rs[mt * 2]);
                atomicAdd(&g_S[R0 + mt * 16 + 8 + (lane >> 2)], rs[mt * 2 + 1]);
            }
        }
    }

    // ---- grid barrier 2 + final reduce on CTA 0 ----
    __syncthreads();
    if (tid == 0) { __threadfence(); atomicAdd(&g_c2, 1); }
    if (blockIdx.x != 0) return;

    if (tid == 0) {
        while (atomicAdd(&g_c2, 0) < NCTA) { }
        __threadfence();
    }
    __syncthreads();

    __shared__ double sh[256];
    double local = 0.0;
    for (int idx = tid; idx < N2; idx += 256)
        local += (double)(2.0f + __logf(g_S[idx] - 1.0f));
    for (int r = tid; r < N; r += 256)
        local -= 2.0 * (double)g_pos[r];
    sh[tid] = local;
    __syncthreads();
    #pragma unroll
    for (int s2 = 128; s2; s2 >>= 1) {
        if (tid < s2) sh[tid] += sh[tid + s2];
        __syncthreads();
    }
    if (tid == 0) {
        out[0] = (float)(sh[0] / (double)N2);
        g_c1 = 0;             // reset barriers for the next graph replay
        g_c2 = 0;
    }
}

// ---------------------------------------------------------------------------
extern "C" void kernel_launch(void* const* d_in, const int* in_sizes, int n_in,
                              void* d_out, int out_size)
{
    const float* zi = (const float*)d_in[0];
    const float* zj = (const float*)d_in[1];
    int N = in_sizes[0] / D;      // 4096

    size_t smem = 3 * (size_t)SBYTES;   // 202752 B
    cudaFuncSetAttribute(fused_kernel,
                         cudaFuncAttributeMaxDynamicSharedMemorySize, (int)smem);
    fused_kernel<<<NCTA, 256, smem>>>(zi, zj, (float*)d_out, N);
}